// round 1
// baseline (speedup 1.0000x reference)
#include <cuda_runtime.h>
#include <math.h>

#define NROWS 12288
#define KDIM  512
#define FDIM  128
#define NB    8192
#define TMIN  (-12.0f)
#define TRANGE 24.0f
#define NCHUNK 96
#define CHUNK  128

// ---------------- scratch (static device globals; no allocation) -------------
__device__ float g_W[FDIM * KDIM];            // normalized weight
__device__ float g_Z[NROWS * FDIM];           // z = x@W^T + b
__device__ float g_s[NROWS];
__device__ float g_t[NROWS];
__device__ int   g_hist[NB];
__device__ int   g_cum[NB];                   // inclusive bucket counts
__device__ int   g_wptr[NB];                  // scatter cursors
__device__ int   g_perm[NROWS];
__device__ float g_ets[NROWS];                // exp(t) in sorted order
__device__ float g_Zs[NROWS * FDIM];          // z permuted to sorted order
__device__ float g_PZ[(NROWS + 1) * FDIM];    // exclusive prefix of Zs
__device__ float g_SEZ[(NROWS + 1) * FDIM];   // inclusive suffix of ets*Zs
__device__ float g_ES[NROWS + 1];             // inclusive suffix of ets
__device__ float g_cA[NCHUNK * FDIM];
__device__ float g_cB[NCHUNK * FDIM];
__device__ float g_cE[NCHUNK];
__device__ float g_cApre[NCHUNK * FDIM];
__device__ float g_cBsuf[NCHUNK * FDIM];
__device__ float g_cEsuf[NCHUNK];

__device__ __forceinline__ int bucket_of(float tv) {
    int q = (int)floorf((tv - TMIN) * (NB / TRANGE));
    return min(max(q, 0), NB - 1);
}

// ---------------- K1: w = g * v / ||v|| --------------------------------------
__global__ void k_prep(const float* __restrict__ v, const float* __restrict__ g) {
    int f = blockIdx.x;
    int tid = threadIdx.x;  // 128
    float ss = 0.f;
    for (int k = tid; k < KDIM; k += 128) { float x = v[f * KDIM + k]; ss += x * x; }
    #pragma unroll
    for (int o = 16; o; o >>= 1) ss += __shfl_xor_sync(0xffffffffu, ss, o);
    __shared__ float sm[4];
    if ((tid & 31) == 0) sm[tid >> 5] = ss;
    __syncthreads();
    float tot = sm[0] + sm[1] + sm[2] + sm[3];
    float c = g[f] / sqrtf(tot);
    for (int k = tid; k < KDIM; k += 128) g_W[f * KDIM + k] = c * v[f * KDIM + k];
}

// ---------------- K2: z = x @ W^T + b ----------------------------------------
// BM=64, BN=128, BK=32, 256 threads, 8x4 micro-tile
__global__ __launch_bounds__(256) void k_gemm(const float* __restrict__ x,
                                              const float* __restrict__ bias) {
    __shared__ float As[32][65];
    __shared__ float Bs[32][129];
    int tid = threadIdx.x;
    int row0 = blockIdx.x * 64;
    int tm0 = (tid >> 5) * 8;
    int tn0 = tid & 31;
    float acc[8][4];
    #pragma unroll
    for (int m = 0; m < 8; m++)
        #pragma unroll
        for (int q = 0; q < 4; q++) acc[m][q] = 0.f;

    for (int k0 = 0; k0 < KDIM; k0 += 32) {
        #pragma unroll
        for (int v = 0; v < 2; v++) {
            int idx = tid + v * 256;
            int r = idx >> 3, kq = idx & 7;
            float4 d = *(const float4*)(x + (size_t)(row0 + r) * KDIM + k0 + kq * 4);
            As[kq * 4 + 0][r] = d.x; As[kq * 4 + 1][r] = d.y;
            As[kq * 4 + 2][r] = d.z; As[kq * 4 + 3][r] = d.w;
        }
        #pragma unroll
        for (int v = 0; v < 4; v++) {
            int idx = tid + v * 256;
            int f = idx >> 3, kq = idx & 7;
            float4 d = *(const float4*)(g_W + (size_t)f * KDIM + k0 + kq * 4);
            Bs[kq * 4 + 0][f] = d.x; Bs[kq * 4 + 1][f] = d.y;
            Bs[kq * 4 + 2][f] = d.z; Bs[kq * 4 + 3][f] = d.w;
        }
        __syncthreads();
        #pragma unroll
        for (int k = 0; k < 32; k++) {
            float ra[8], rb[4];
            #pragma unroll
            for (int m = 0; m < 8; m++) ra[m] = As[k][tm0 + m];
            #pragma unroll
            for (int q = 0; q < 4; q++) rb[q] = Bs[k][tn0 + 32 * q];
            #pragma unroll
            for (int m = 0; m < 8; m++)
                #pragma unroll
                for (int q = 0; q < 4; q++) acc[m][q] = fmaf(ra[m], rb[q], acc[m][q]);
        }
        __syncthreads();
    }
    #pragma unroll
    for (int m = 0; m < 8; m++) {
        int r = row0 + tm0 + m;
        #pragma unroll
        for (int q = 0; q < 4; q++) {
            int f = tn0 + 32 * q;
            g_Z[(size_t)r * FDIM + f] = acc[m][q] + bias[f];
        }
    }
}

// ---------------- K3: s = z@a_src, t = z@a_dst -------------------------------
__global__ void k_st(const float* __restrict__ aw) {
    int warp = threadIdx.x >> 5, lane = threadIdx.x & 31;
    int i = blockIdx.x * 4 + warp;
    float s = 0.f, t = 0.f;
    #pragma unroll
    for (int q = 0; q < 4; q++) {
        int f = lane + 32 * q;
        float z = g_Z[(size_t)i * FDIM + f];
        s += z * aw[f];
        t += z * aw[FDIM + f];
    }
    #pragma unroll
    for (int o = 16; o; o >>= 1) {
        s += __shfl_xor_sync(0xffffffffu, s, o);
        t += __shfl_xor_sync(0xffffffffu, t, o);
    }
    if (!lane) { g_s[i] = s; g_t[i] = t; }
}

// ---------------- K4: histogram ----------------------------------------------
__global__ void k_zero() {
    int i = blockIdx.x * 1024 + threadIdx.x;
    g_hist[i] = 0;
}
__global__ void k_hist() {
    int j = blockIdx.x * 1024 + threadIdx.x;
    atomicAdd(&g_hist[bucket_of(g_t[j])], 1);
}

// ---------------- K5: scan histogram (1 block, 1024 thr) ---------------------
__global__ __launch_bounds__(1024) void k_scanhist() {
    __shared__ int sm[1024];
    int tid = threadIdx.x;
    int loc[8]; int tsum = 0;
    #pragma unroll
    for (int r = 0; r < 8; r++) { loc[r] = g_hist[tid * 8 + r]; tsum += loc[r]; }
    sm[tid] = tsum;
    __syncthreads();
    int val = tsum;
    for (int off = 1; off < 1024; off <<= 1) {
        int v = (tid >= off) ? sm[tid - off] : 0;
        __syncthreads();
        val += v;
        sm[tid] = val;
        __syncthreads();
    }
    int run = val - tsum;  // exclusive prefix
    #pragma unroll
    for (int r = 0; r < 8; r++) {
        int q = tid * 8 + r;
        g_wptr[q] = run;
        run += loc[r];
        g_cum[q] = run;
    }
}

// ---------------- K6: counting-sort scatter ----------------------------------
__global__ void k_scatter() {
    int j = blockIdx.x * 1024 + threadIdx.x;
    float tv = g_t[j];
    int q = bucket_of(tv);
    int pos = atomicAdd(&g_wptr[q], 1);
    g_perm[pos] = j;
    g_ets[pos] = __expf(tv);
}

// ---------------- K7: permute z rows to sorted order -------------------------
__global__ __launch_bounds__(128) void k_permute() {
    int c = blockIdx.x, f = threadIdx.x;
    for (int r = 0; r < CHUNK; r++) {
        int p = c * CHUNK + r;
        int src = g_perm[p];
        g_Zs[(size_t)p * FDIM + f] = g_Z[(size_t)src * FDIM + f];
    }
}

// ---------------- K8-K10: 3-phase vector scans -------------------------------
__global__ __launch_bounds__(160) void k_phase1() {
    int c = blockIdx.x, f = threadIdx.x;
    if (f < FDIM) {
        float a = 0.f, bb = 0.f;
        for (int k = 0; k < CHUNK; k++) {
            int p = c * CHUNK + k;
            float zv = g_Zs[(size_t)p * FDIM + f];
            a += zv;
            bb += g_ets[p] * zv;
        }
        g_cA[c * FDIM + f] = a;
        g_cB[c * FDIM + f] = bb;
    } else if (f == FDIM) {
        float e = 0.f;
        for (int k = 0; k < CHUNK; k++) e += g_ets[c * CHUNK + k];
        g_cE[c] = e;
    }
}

__global__ __launch_bounds__(160) void k_phase2() {
    int f = threadIdx.x;
    if (f < FDIM) {
        float run = 0.f;
        for (int c = 0; c < NCHUNK; c++) {
            g_cApre[c * FDIM + f] = run;
            run += g_cA[c * FDIM + f];
        }
        g_PZ[(size_t)NROWS * FDIM + f] = run;  // total sum at p=NROWS
        float runb = 0.f;
        for (int c = NCHUNK - 1; c >= 0; c--) {
            g_cBsuf[c * FDIM + f] = runb;
            runb += g_cB[c * FDIM + f];
        }
        g_SEZ[(size_t)NROWS * FDIM + f] = 0.f;
    } else if (f == FDIM) {
        float run = 0.f;
        for (int c = NCHUNK - 1; c >= 0; c--) {
            g_cEsuf[c] = run;
            run += g_cE[c];
        }
        g_ES[NROWS] = 0.f;
    }
}

__global__ __launch_bounds__(160) void k_phase3() {
    int c = blockIdx.x, f = threadIdx.x;
    if (f < FDIM) {
        float run = g_cApre[c * FDIM + f];
        for (int k = 0; k < CHUNK; k++) {
            int p = c * CHUNK + k;
            g_PZ[(size_t)p * FDIM + f] = run;
            run += g_Zs[(size_t)p * FDIM + f];
        }
        float runb = g_cBsuf[c * FDIM + f];
        for (int k = CHUNK - 1; k >= 0; k--) {
            int p = c * CHUNK + k;
            runb += g_ets[p] * g_Zs[(size_t)p * FDIM + f];
            g_SEZ[(size_t)p * FDIM + f] = runb;
        }
    } else if (f == FDIM) {
        float run = g_cEsuf[c];
        for (int k = CHUNK - 1; k >= 0; k--) {
            int p = c * CHUNK + k;
            run += g_ets[p];
            g_ES[p] = run;
        }
    }
}

// ---------------- K11: combine + residual + row softmax ----------------------
__global__ __launch_bounds__(128) void k_final(float* __restrict__ out) {
    int i = blockIdx.x, f = threadIdx.x;
    int lane = f & 31, warp = f >> 5;
    __shared__ float red[4];
    float si = g_s[i];
    int q = bucket_of(-si);
    int p = g_cum[q];                    // # of j treated as "plain" (weight 1)
    float es = __expf(si);
    float denom = (float)p + es * g_ES[p];
    float num = g_PZ[(size_t)p * FDIM + f] + es * g_SEZ[(size_t)p * FDIM + f];
    float z2 = num / denom + g_Z[(size_t)i * FDIM + f];
    // softmax over 128 features
    float m = z2;
    #pragma unroll
    for (int o = 16; o; o >>= 1) m = fmaxf(m, __shfl_xor_sync(0xffffffffu, m, o));
    if (!lane) red[warp] = m;
    __syncthreads();
    m = fmaxf(fmaxf(red[0], red[1]), fmaxf(red[2], red[3]));
    float e = __expf(z2 - m);
    float ssum = e;
    #pragma unroll
    for (int o = 16; o; o >>= 1) ssum += __shfl_xor_sync(0xffffffffu, ssum, o);
    __syncthreads();
    if (!lane) red[warp] = ssum;
    __syncthreads();
    ssum = red[0] + red[1] + red[2] + red[3];
    out[(size_t)i * FDIM + f] = e / ssum;
}

// ---------------- launch ------------------------------------------------------
extern "C" void kernel_launch(void* const* d_in, const int* in_sizes, int n_in,
                              void* d_out, int out_size) {
    const float* x  = (const float*)d_in[0];  // (12288, 512)
    const float* v  = (const float*)d_in[1];  // (128, 512)
    const float* g  = (const float*)d_in[2];  // (128, 1)
    const float* b  = (const float*)d_in[3];  // (128,)
    const float* aw = (const float*)d_in[4];  // (256, 1)
    float* out = (float*)d_out;               // (12288, 128)

    k_prep<<<FDIM, 128>>>(v, g);
    k_gemm<<<NROWS / 64, 256>>>(x, b);
    k_st<<<NROWS / 4, 128>>>(aw);
    k_zero<<<NB / 1024, 1024>>>();
    k_hist<<<NROWS / 1024, 1024>>>();
    k_scanhist<<<1, 1024>>>();
    k_scatter<<<NROWS / 1024, 1024>>>();
    k_permute<<<NCHUNK, 128>>>();
    k_phase1<<<NCHUNK, 160>>>();
    k_phase2<<<1, 160>>>();
    k_phase3<<<NCHUNK, 160>>>();
    k_final<<<NROWS, 128>>>(out);
}

// round 3
// speedup vs baseline: 1.8564x; 1.8564x over previous
#include <cuda_runtime.h>
#include <math.h>

#define NROWS 12288
#define KDIM  512
#define FDIM  128
#define NB    8192
#define TMIN  (-12.0f)
#define TRANGE 24.0f
#define NCHUNK 192
#define CHUNK  64

typedef unsigned long long ull;

// ---------------- scratch ------------------------------------------------------
__device__ float g_W[FDIM * KDIM];
__device__ float g_Z[NROWS * FDIM];
__device__ float g_s[NROWS];
__device__ float g_t[NROWS];
__device__ int   g_hist[NB];
__device__ int   g_cum[NB];
__device__ int   g_wptr[NB];
__device__ int   g_perm[NROWS];
__device__ float g_ets[NROWS];
__device__ float g_PZ[(NROWS + 1) * FDIM];
__device__ float g_SEZ[(NROWS + 1) * FDIM];
__device__ float g_ES[NROWS + 1];
__device__ float g_cA[NCHUNK * FDIM];
__device__ float g_cB[NCHUNK * FDIM];
__device__ float g_cE[NCHUNK];
__device__ float g_cApre[NCHUNK * FDIM];
__device__ float g_cBsuf[NCHUNK * FDIM];
__device__ float g_cEsuf[NCHUNK];

__device__ __forceinline__ int bucket_of(float tv) {
    int q = (int)floorf((tv - TMIN) * (NB / TRANGE));
    return min(max(q, 0), NB - 1);
}

__device__ __forceinline__ void ffma2(ull& d, ull a, ull b, ull c) {
    asm("fma.rn.f32x2 %0, %1, %2, %3;" : "=l"(d) : "l"(a), "l"(b), "l"(c));
}
__device__ __forceinline__ ull dup2(float x) {
    ull d; asm("mov.b64 %0, {%1, %1};" : "=l"(d) : "f"(x)); return d;
}
__device__ __forceinline__ void unpack2(ull v, float& lo, float& hi) {
    asm("mov.b64 {%0, %1}, %2;" : "=f"(lo), "=f"(hi) : "l"(v));
}

// ---------------- K1: w = g * v / ||v|| ---------------------------------------
__global__ void k_prep(const float* __restrict__ v, const float* __restrict__ g) {
    int f = blockIdx.x;
    int tid = threadIdx.x;  // 128
    float ss = 0.f;
    for (int k = tid; k < KDIM; k += 128) { float x = v[f * KDIM + k]; ss += x * x; }
    #pragma unroll
    for (int o = 16; o; o >>= 1) ss += __shfl_xor_sync(0xffffffffu, ss, o);
    __shared__ float sm[4];
    if ((tid & 31) == 0) sm[tid >> 5] = ss;
    __syncthreads();
    float tot = sm[0] + sm[1] + sm[2] + sm[3];
    float c = g[f] / sqrtf(tot);
    for (int k = tid; k < KDIM; k += 128) g_W[f * KDIM + k] = c * v[f * KDIM + k];
}

// ---------------- K2: zero hist -----------------------------------------------
__global__ void k_zero() {
    g_hist[blockIdx.x * 1024 + threadIdx.x] = 0;
}

// ---------------- K3: z = x@W^T + b  (FFMA2), fused s,t + hist ----------------
// BM=32, BN=128, BK=32, 128 threads. Per thread: 4 rows (paired) x 8 cols.
__global__ __launch_bounds__(128) void k_gemm(const float* __restrict__ x,
                                              const float* __restrict__ bias,
                                              const float* __restrict__ aw) {
    __shared__ float As[32][34];    // [k][row]
    __shared__ float Bs[32][130];   // [k][col]
    int tid = threadIdx.x;
    int lane = tid & 31, w = tid >> 5;
    int row0 = blockIdx.x * 32;
    int mr = w * 8 + (lane >> 4) * 4;       // 4 consecutive rows (even base)
    int cl = lane & 15;                     // cols: cl + 16*j, j=0..7

    ull acc[2][8];
    #pragma unroll
    for (int m = 0; m < 2; m++)
        #pragma unroll
        for (int j = 0; j < 8; j++) acc[m][j] = 0ull;

    int ar = tid >> 2, akq = (tid & 3) * 4;
    int bf = tid >> 3, bkq = (tid & 7) * 4;

    for (int k0 = 0; k0 < KDIM; k0 += 32) {
        float4 d0 = *(const float4*)(x + (size_t)(row0 + ar) * KDIM + k0 + akq);
        float4 d1 = *(const float4*)(x + (size_t)(row0 + ar) * KDIM + k0 + akq + 16);
        float4 wv[8];
        #pragma unroll
        for (int u = 0; u < 8; u++)
            wv[u] = *(const float4*)(g_W + (size_t)(u * 16 + bf) * KDIM + k0 + bkq);
        __syncthreads();
        As[akq + 0][ar] = d0.x; As[akq + 1][ar] = d0.y;
        As[akq + 2][ar] = d0.z; As[akq + 3][ar] = d0.w;
        As[akq + 16][ar] = d1.x; As[akq + 17][ar] = d1.y;
        As[akq + 18][ar] = d1.z; As[akq + 19][ar] = d1.w;
        #pragma unroll
        for (int u = 0; u < 8; u++) {
            int f = u * 16 + bf;
            Bs[bkq + 0][f] = wv[u].x; Bs[bkq + 1][f] = wv[u].y;
            Bs[bkq + 2][f] = wv[u].z; Bs[bkq + 3][f] = wv[u].w;
        }
        __syncthreads();
        #pragma unroll 8
        for (int k = 0; k < 32; k++) {
            ull a01 = *(const ull*)&As[k][mr];
            ull a23 = *(const ull*)&As[k][mr + 2];
            #pragma unroll
            for (int j = 0; j < 8; j++) {
                ull bb = dup2(Bs[k][cl + 16 * j]);
                ffma2(acc[0][j], a01, bb, acc[0][j]);
                ffma2(acc[1][j], a23, bb, acc[1][j]);
            }
        }
    }

    // epilogue: bias, store Z, fused s,t partials
    float ps[4] = {0.f, 0.f, 0.f, 0.f};
    float pt[4] = {0.f, 0.f, 0.f, 0.f};
    #pragma unroll
    for (int j = 0; j < 8; j++) {
        int c = cl + 16 * j;
        float bv = bias[c];
        float asrc = aw[c], adst = aw[FDIM + c];
        float z0, z1, z2, z3;
        unpack2(acc[0][j], z0, z1);
        unpack2(acc[1][j], z2, z3);
        z0 += bv; z1 += bv; z2 += bv; z3 += bv;
        g_Z[(size_t)(row0 + mr + 0) * FDIM + c] = z0;
        g_Z[(size_t)(row0 + mr + 1) * FDIM + c] = z1;
        g_Z[(size_t)(row0 + mr + 2) * FDIM + c] = z2;
        g_Z[(size_t)(row0 + mr + 3) * FDIM + c] = z3;
        ps[0] += asrc * z0; ps[1] += asrc * z1; ps[2] += asrc * z2; ps[3] += asrc * z3;
        pt[0] += adst * z0; pt[1] += adst * z1; pt[2] += adst * z2; pt[3] += adst * z3;
    }
    #pragma unroll
    for (int o = 1; o < 16; o <<= 1) {
        #pragma unroll
        for (int r = 0; r < 4; r++) {
            ps[r] += __shfl_xor_sync(0xffffffffu, ps[r], o);
            pt[r] += __shfl_xor_sync(0xffffffffu, pt[r], o);
        }
    }
    if (cl == 0) {
        #pragma unroll
        for (int r = 0; r < 4; r++) {
            int row = row0 + mr + r;
            g_s[row] = ps[r];
            g_t[row] = pt[r];
            atomicAdd(&g_hist[bucket_of(pt[r])], 1);
        }
    }
}

// ---------------- K4: scan histogram ------------------------------------------
__global__ __launch_bounds__(1024) void k_scanhist() {
    __shared__ int sm[1024];
    int tid = threadIdx.x;
    int loc[8]; int tsum = 0;
    #pragma unroll
    for (int r = 0; r < 8; r++) { loc[r] = g_hist[tid * 8 + r]; tsum += loc[r]; }
    sm[tid] = tsum;
    __syncthreads();
    int val = tsum;
    for (int off = 1; off < 1024; off <<= 1) {
        int v = (tid >= off) ? sm[tid - off] : 0;
        __syncthreads();
        val += v;
        sm[tid] = val;
        __syncthreads();
    }
    int run = val - tsum;
    #pragma unroll
    for (int r = 0; r < 8; r++) {
        int q = tid * 8 + r;
        g_wptr[q] = run;
        run += loc[r];
        g_cum[q] = run;
    }
}

// ---------------- K5: counting-sort scatter -----------------------------------
__global__ void k_scatter() {
    int j = blockIdx.x * 1024 + threadIdx.x;
    float tv = g_t[j];
    int q = bucket_of(tv);
    int pos = atomicAdd(&g_wptr[q], 1);
    g_perm[pos] = j;
    g_ets[pos] = __expf(tv);
}

// ---------------- K6: chunk aggregates (gathered) -----------------------------
__global__ __launch_bounds__(160) void k_phase1() {
    int c = blockIdx.x, f = threadIdx.x;
    if (f < FDIM) {
        float a = 0.f, bb = 0.f;
        for (int k = 0; k < CHUNK; k++) {
            int p = c * CHUNK + k;
            int src = g_perm[p];
            float zv = g_Z[(size_t)src * FDIM + f];
            a += zv;
            bb += g_ets[p] * zv;
        }
        g_cA[c * FDIM + f] = a;
        g_cB[c * FDIM + f] = bb;
    } else {
        int l = f - FDIM;  // 0..31
        float e = 0.f;
        for (int k = l; k < CHUNK; k += 32) e += g_ets[c * CHUNK + k];
        #pragma unroll
        for (int o = 16; o; o >>= 1) e += __shfl_xor_sync(0xffffffffu, e, o);
        if (l == 0) g_cE[c] = e;
    }
}

// ---------------- K7: inter-chunk scans (warp per feature) --------------------
// NCHUNK=192 = 32 lanes * 6
__global__ __launch_bounds__(256) void k_phase2() {
    int lane = threadIdx.x & 31;
    if (blockIdx.x < 16) {
        int f = blockIdx.x * 8 + (threadIdx.x >> 5);  // 0..127
        int cb = lane * 6;
        // exclusive prefix of cA
        float a[6], le[6]; float s = 0.f;
        #pragma unroll
        for (int i = 0; i < 6; i++) a[i] = g_cA[(cb + i) * FDIM + f];
        #pragma unroll
        for (int i = 0; i < 6; i++) { le[i] = s; s += a[i]; }
        float inc = s;
        #pragma unroll
        for (int o = 1; o < 32; o <<= 1) {
            float v = __shfl_up_sync(0xffffffffu, inc, o);
            if (lane >= o) inc += v;
        }
        float ex = inc - s;
        #pragma unroll
        for (int i = 0; i < 6; i++) g_cApre[(cb + i) * FDIM + f] = ex + le[i];
        if (lane == 31) g_PZ[(size_t)NROWS * FDIM + f] = inc;
        // exclusive suffix of cB (scan over reversed order)
        s = 0.f;
        #pragma unroll
        for (int i = 0; i < 6; i++) a[i] = g_cB[(NCHUNK - 1 - (cb + i)) * FDIM + f];
        #pragma unroll
        for (int i = 0; i < 6; i++) { le[i] = s; s += a[i]; }
        inc = s;
        #pragma unroll
        for (int o = 1; o < 32; o <<= 1) {
            float v = __shfl_up_sync(0xffffffffu, inc, o);
            if (lane >= o) inc += v;
        }
        ex = inc - s;
        #pragma unroll
        for (int i = 0; i < 6; i++) g_cBsuf[(NCHUNK - 1 - (cb + i)) * FDIM + f] = ex + le[i];
        if (lane == 0) g_SEZ[(size_t)NROWS * FDIM + f] = 0.f;
    } else if (threadIdx.x < 32) {
        // exclusive suffix of cE
        int cb = lane * 6;
        float a[6], le[6]; float s = 0.f;
        #pragma unroll
        for (int i = 0; i < 6; i++) a[i] = g_cE[NCHUNK - 1 - (cb + i)];
        #pragma unroll
        for (int i = 0; i < 6; i++) { le[i] = s; s += a[i]; }
        float inc = s;
        #pragma unroll
        for (int o = 1; o < 32; o <<= 1) {
            float v = __shfl_up_sync(0xffffffffu, inc, o);
            if (lane >= o) inc += v;
        }
        float ex = inc - s;
        #pragma unroll
        for (int i = 0; i < 6; i++) g_cEsuf[NCHUNK - 1 - (cb + i)] = ex + le[i];
        if (lane == 0) g_ES[NROWS] = 0.f;
    }
}

// ---------------- K8: intra-chunk scans, one forward pass ---------------------
// PZ[p] = exclusive prefix; SEZ[p] = chunk-total suffix minus exclusive prefix.
__global__ __launch_bounds__(160) void k_phase3() {
    int c = blockIdx.x, f = threadIdx.x;
    if (f < FDIM) {
        float runA = g_cApre[c * FDIM + f];
        float S0b = g_cBsuf[c * FDIM + f] + g_cB[c * FDIM + f];
        float preB = 0.f;
        for (int k = 0; k < CHUNK; k++) {
            int p = c * CHUNK + k;
            int src = g_perm[p];
            float zv = g_Z[(size_t)src * FDIM + f];
            float e = g_ets[p];
            g_PZ[(size_t)p * FDIM + f] = runA;
            g_SEZ[(size_t)p * FDIM + f] = S0b - preB;
            runA += zv;
            preB += e * zv;
        }
    } else if (f == FDIM) {
        float S0 = g_cEsuf[c] + g_cE[c];
        float pre = 0.f;
        for (int k = 0; k < CHUNK; k++) {
            int p = c * CHUNK + k;
            g_ES[p] = S0 - pre;
            pre += g_ets[p];
        }
    }
}

// ---------------- K9: combine + residual + row softmax ------------------------
__global__ __launch_bounds__(128) void k_final(float* __restrict__ out) {
    int i = blockIdx.x, f = threadIdx.x;
    int lane = f & 31, warp = f >> 5;
    __shared__ float red[4];
    float si = g_s[i];
    int q = bucket_of(-si);
    int p = g_cum[q];
    float es = __expf(si);
    float denom = (float)p + es * g_ES[p];
    float num = g_PZ[(size_t)p * FDIM + f] + es * g_SEZ[(size_t)p * FDIM + f];
    float z2 = num / denom + g_Z[(size_t)i * FDIM + f];
    float m = z2;
    #pragma unroll
    for (int o = 16; o; o >>= 1) m = fmaxf(m, __shfl_xor_sync(0xffffffffu, m, o));
    if (!lane) red[warp] = m;
    __syncthreads();
    m = fmaxf(fmaxf(red[0], red[1]), fmaxf(red[2], red[3]));
    float e = __expf(z2 - m);
    float ssum = e;
    #pragma unroll
    for (int o = 16; o; o >>= 1) ssum += __shfl_xor_sync(0xffffffffu, ssum, o);
    __syncthreads();
    if (!lane) red[warp] = ssum;
    __syncthreads();
    ssum = red[0] + red[1] + red[2] + red[3];
    out[(size_t)i * FDIM + f] = e / ssum;
}

// ---------------- launch ------------------------------------------------------
extern "C" void kernel_launch(void* const* d_in, const int* in_sizes, int n_in,
                              void* d_out, int out_size) {
    const float* x  = (const float*)d_in[0];
    const float* v  = (const float*)d_in[1];
    const float* g  = (const float*)d_in[2];
    const float* b  = (const float*)d_in[3];
    const float* aw = (const float*)d_in[4];
    float* out = (float*)d_out;

    k_prep<<<FDIM, 128>>>(v, g);
    k_zero<<<NB / 1024, 1024>>>();
    k_gemm<<<NROWS / 32, 128>>>(x, b, aw);
    k_scanhist<<<1, 1024>>>();
    k_scatter<<<NROWS / 1024, 1024>>>();
    k_phase1<<<NCHUNK, 160>>>();
    k_phase2<<<17, 256>>>();
    k_phase3<<<NCHUNK, 160>>>();
    k_final<<<NROWS, 128>>>(out);
}